// round 7
// baseline (speedup 1.0000x reference)
#include <cuda_runtime.h>
#include <cstdint>

#define MAX_N    8192
#define MAX_H2   256
#define MAX_H    128

__device__ uint32_t g_h1hi[MAX_N * MAX_H2];     // tf32-hi of relu(x@W1+b1)
__device__ uint32_t g_h1lo[MAX_N * MAX_H2];     // tf32-lo residual
__device__ uint32_t g_allh_tf[MAX_N * MAX_H];   // tf32 bits of all_h
__device__ float    g_W1T[MAX_H2 * MAX_H2];     // W1^T [256n][256k]
__device__ float    g_W2T[MAX_H  * MAX_H2];     // W2^T [128n][256k]

__device__ __forceinline__ uint32_t f2tf32(float f) {
    uint32_t u;
    asm("cvt.rna.tf32.f32 %0, %1;" : "=r"(u) : "f"(f));
    return u;
}
__device__ __forceinline__ void mma_tf32(float& c0, float& c1, float& c2, float& c3,
                                         uint32_t a0, uint32_t a1, uint32_t a2, uint32_t a3,
                                         uint32_t b0, uint32_t b1) {
    asm volatile(
        "mma.sync.aligned.m16n8k8.row.col.f32.tf32.tf32.f32 "
        "{%0,%1,%2,%3}, {%4,%5,%6,%7}, {%8,%9}, {%0,%1,%2,%3};"
        : "+f"(c0), "+f"(c1), "+f"(c2), "+f"(c3)
        : "r"(a0), "r"(a1), "r"(a2), "r"(a3), "r"(b0), "r"(b1));
}

// ===========================================================================
// Packed fragment smem layout (per 32-k chunk row of 32 u32 = 128B):
//   logical k -> packed p = (k>>4)*16 + (k&3)*4 + ((k>>3)&1)*2 + ((k>>2)&1)
//   so thread qd's LDS.128 at u = ks2*4+qd yields (k0+qd, k0+qd+4) for the
//   two k-steps ks=2*ks2, 2*ks2+1.  16B-unit swizzle: u ^= (row&1)<<2
//   -> conflict-free LDS.128 across the 8-row fragment access.
// ===========================================================================
__device__ __forceinline__ uint4 ld_frag(const uint32_t* buf, int row, int ks2, int qd) {
    const int u = ((ks2 << 2) + qd) ^ ((row & 1) << 2);
    return *reinterpret_cast<const uint4*>(buf + row * 32 + (u << 2));
}
// store float4 worth of k = seg*4 .. seg*4+3 into packed layout
__device__ __forceinline__ void sts_packed4(uint32_t* buf, int row, int seg, uint4 v) {
    const int lo2 = ((seg >> 1) & 1) * 2 + (seg & 1);
    const int hi  = (seg >> 2) << 2;
    const int sw  = (row & 1) << 2;
    uint32_t* base = buf + row * 32 + lo2;
    base[((hi + 0) ^ sw) << 2] = v.x;
    base[((hi + 1) ^ sw) << 2] = v.y;
    base[((hi + 2) ^ sw) << 2] = v.z;
    base[((hi + 3) ^ sw) << 2] = v.w;
}
__device__ __forceinline__ uint4 split_hi(float4 v, uint4& lo) {
    uint4 hi = make_uint4(f2tf32(v.x), f2tf32(v.y), f2tf32(v.z), f2tf32(v.w));
    lo = make_uint4(f2tf32(v.x - __uint_as_float(hi.x)),
                    f2tf32(v.y - __uint_as_float(hi.y)),
                    f2tf32(v.z - __uint_as_float(hi.z)),
                    f2tf32(v.w - __uint_as_float(hi.w)));
    return hi;
}

// ===========================================================================
// recons = X @ X^T, X pre-converted tf32 bits [N,128].
// 128x128 tile pair (bi<=bj) per CTA, 8 warps (2x4), warp tile 64x32.
// K=128 in 4 chunks of 32, double-buffered via register prefetch.
// smem: 2 A bufs + 2 B bufs of 128x32 u32 (16KB each) = 64KB; mirror
// staging reuses it as float[128][132] (67584 B total allocation).
// ===========================================================================
#define TPAD  132
#define R_SMEM_BYTES (128 * TPAD * 4)        // 67584 (>= 65536 buffer use)

__global__ __launch_bounds__(256, 2)
void recons_mma(const uint32_t* __restrict__ Xt, float* __restrict__ out, int NB, int NN)
{
    extern __shared__ uint32_t sm_u[];
    const int tid  = threadIdx.x;
    const int lane = tid & 31;
    const int wid  = tid >> 5;
    const int warp_m = wid >> 2;
    const int warp_n = wid & 3;
    const int grp  = lane >> 2;
    const int qd   = lane & 3;

    int rem = blockIdx.x, bi = 0;
    while (rem >= NB - bi) { rem -= NB - bi; bi++; }
    const int bj = bi + rem;
    const bool diag = (bi == bj);

    const uint32_t* Ap = Xt + (size_t)bi * 128 * 128;
    const uint32_t* Bp = Xt + (size_t)bj * 128 * 128;

    uint32_t* Abuf[2] = { sm_u,            sm_u + 4096 };
    uint32_t* Bbuf[2] = { sm_u + 8192,     sm_u + 12288 };

    const int lrow = tid >> 3;          // 0..31 base row (stride 32 over 4 its? no:)
    // loader mapping: i = tid + 256*it -> row = i>>3 (0..127), seg = i&7
    uint4 ra[4], rb[4];

    auto ldg_chunk = [&](int kc) {
#pragma unroll
        for (int it = 0; it < 4; it++) {
            const int i = tid + 256 * it;
            const int row = i >> 3, seg = i & 7;
            ra[it] = *reinterpret_cast<const uint4*>(Ap + (size_t)row * 128 + kc * 32 + seg * 4);
        }
        if (!diag) {
#pragma unroll
            for (int it = 0; it < 4; it++) {
                const int i = tid + 256 * it;
                const int row = i >> 3, seg = i & 7;
                rb[it] = *reinterpret_cast<const uint4*>(Bp + (size_t)row * 128 + kc * 32 + seg * 4);
            }
        }
    };
    auto sts_chunk = [&](int b) {
#pragma unroll
        for (int it = 0; it < 4; it++) {
            const int i = tid + 256 * it;
            sts_packed4(Abuf[b], i >> 3, i & 7, ra[it]);
        }
        if (!diag) {
#pragma unroll
            for (int it = 0; it < 4; it++) {
                const int i = tid + 256 * it;
                sts_packed4(Bbuf[b], i >> 3, i & 7, rb[it]);
            }
        }
    };

    float acc[4][4][4];
#pragma unroll
    for (int mt = 0; mt < 4; mt++)
#pragma unroll
        for (int nt = 0; nt < 4; nt++)
#pragma unroll
            for (int q = 0; q < 4; q++) acc[mt][nt][q] = 0.f;

    ldg_chunk(0);
    sts_chunk(0);
    __syncthreads();

    for (int kc = 0; kc < 4; kc++) {
        if (kc < 3) ldg_chunk(kc + 1);
        const int b = kc & 1;
        const uint32_t* As = Abuf[b];
        const uint32_t* Bs = diag ? Abuf[b] : Bbuf[b];

#pragma unroll
        for (int ks2 = 0; ks2 < 2; ks2++) {
            uint4 bf[4];
#pragma unroll
            for (int nt = 0; nt < 4; nt++)
                bf[nt] = ld_frag(Bs, warp_n * 32 + nt * 8 + grp, ks2, qd);
#pragma unroll
            for (int mt = 0; mt < 4; mt++) {
                const int rowA = warp_m * 64 + mt * 16 + grp;
                uint4 aE = ld_frag(As, rowA,     ks2, qd);
                uint4 aO = ld_frag(As, rowA + 8, ks2, qd);
#pragma unroll
                for (int nt = 0; nt < 4; nt++) {
                    mma_tf32(acc[mt][nt][0], acc[mt][nt][1], acc[mt][nt][2], acc[mt][nt][3],
                             aE.x, aO.x, aE.y, aO.y, bf[nt].x, bf[nt].y);
                    mma_tf32(acc[mt][nt][0], acc[mt][nt][1], acc[mt][nt][2], acc[mt][nt][3],
                             aE.z, aO.z, aE.w, aO.w, bf[nt].z, bf[nt].w);
                }
            }
        }
        __syncthreads();
        if (kc < 3) { sts_chunk((kc + 1) & 1); __syncthreads(); }
    }

    // ---- direct tile store ----
#pragma unroll
    for (int mt = 0; mt < 4; mt++) {
        const int r0 = bi * 128 + warp_m * 64 + mt * 16 + grp;
#pragma unroll
        for (int nt = 0; nt < 4; nt++) {
            const int c0 = bj * 128 + warp_n * 32 + nt * 8 + 2 * qd;
            *reinterpret_cast<float2*>(out + (size_t)r0 * NN + c0) =
                make_float2(acc[mt][nt][0], acc[mt][nt][1]);
            *reinterpret_cast<float2*>(out + (size_t)(r0 + 8) * NN + c0) =
                make_float2(acc[mt][nt][2], acc[mt][nt][3]);
        }
    }

    // ---- mirror tile via smem transpose staging ----
    if (!diag) {
        float* sT = reinterpret_cast<float*>(sm_u);
#pragma unroll
        for (int mt = 0; mt < 4; mt++) {
            const int r = warp_m * 64 + mt * 16 + grp;
#pragma unroll
            for (int nt = 0; nt < 4; nt++) {
                const int c = warp_n * 32 + nt * 8 + 2 * qd;
                sT[c * TPAD + r]           = acc[mt][nt][0];
                sT[(c + 1) * TPAD + r]     = acc[mt][nt][1];
                sT[c * TPAD + r + 8]       = acc[mt][nt][2];
                sT[(c + 1) * TPAD + r + 8] = acc[mt][nt][3];
            }
        }
        __syncthreads();
#pragma unroll
        for (int it = 0; it < 16; it++) {
            const int i = tid + 256 * it;
            const int rc = i >> 5, q = i & 31;
            float4 v = *reinterpret_cast<const float4*>(sT + rc * TPAD + q * 4);
            *reinterpret_cast<float4*>(out + (size_t)(bj * 128 + rc) * NN + bi * 128 + q * 4) = v;
        }
    }
    (void)lrow;
}

// ===========================================================================
// 3xTF32 MLP GEMM with packed fragment layout.
// APRE=false: A is f32, split hi/lo in loader.
// APRE=true:  A given as pre-split u32 planes (Ahg/Alg).
// Outputs (optional): Chi/Clo u32 planes, C2 f32, Ctf tf32 bits.
// ===========================================================================
template<int BM, bool APRE>
__global__ __launch_bounds__(256)
void gemm3t(const float* __restrict__ A,
            const uint32_t* __restrict__ Ahg, const uint32_t* __restrict__ Alg,
            const float* __restrict__ WT, const float* __restrict__ bias,
            uint32_t* __restrict__ Chi, uint32_t* __restrict__ Clo,
            float* __restrict__ C2, uint32_t* __restrict__ Ctf,
            int K, int Nout, float scale)
{
    constexpr int MT = BM / 32;
    extern __shared__ uint32_t sm_u[];
    uint32_t* Ahi = sm_u;
    uint32_t* Alo = sm_u + BM * 32;
    uint32_t* Bhi = sm_u + 2 * BM * 32;
    uint32_t* Blo = sm_u + 2 * BM * 32 + 128 * 32;

    const int tid  = threadIdx.x;
    const int lane = tid & 31;
    const int wid  = tid >> 5;
    const int warp_m = wid >> 2;
    const int warp_n = wid & 3;
    const int grp  = lane >> 2;
    const int qd   = lane & 3;
    const int bm = blockIdx.x * BM;
    const int bn = blockIdx.y * 128;

    float acc[MT][4][4];
#pragma unroll
    for (int mt = 0; mt < MT; mt++)
#pragma unroll
        for (int nt = 0; nt < 4; nt++)
#pragma unroll
            for (int q = 0; q < 4; q++) acc[mt][nt][q] = 0.f;

    for (int kc = 0; kc < K; kc += 32) {
        // A chunk
#pragma unroll
        for (int it = 0; it < BM * 8 / 256; it++) {
            const int i = tid + 256 * it;
            const int row = i >> 3, seg = i & 7;
            if (APRE) {
                uint4 h = *reinterpret_cast<const uint4*>(Ahg + (size_t)(bm + row) * K + kc + seg * 4);
                uint4 l = *reinterpret_cast<const uint4*>(Alg + (size_t)(bm + row) * K + kc + seg * 4);
                sts_packed4(Ahi, row, seg, h);
                sts_packed4(Alo, row, seg, l);
            } else {
                float4 v = *reinterpret_cast<const float4*>(A + (size_t)(bm + row) * K + kc + seg * 4);
                uint4 l, h = split_hi(v, l);
                sts_packed4(Ahi, row, seg, h);
                sts_packed4(Alo, row, seg, l);
            }
        }
        // B chunk (from f32 WT)
#pragma unroll
        for (int it = 0; it < 4; it++) {
            const int i = tid + 256 * it;
            const int row = i >> 3, seg = i & 7;
            float4 v = *reinterpret_cast<const float4*>(WT + (size_t)(bn + row) * K + kc + seg * 4);
            uint4 l, h = split_hi(v, l);
            sts_packed4(Bhi, row, seg, h);
            sts_packed4(Blo, row, seg, l);
        }
        __syncthreads();

#pragma unroll
        for (int ks2 = 0; ks2 < 2; ks2++) {
            uint4 bh[4], bl[4];
#pragma unroll
            for (int nt = 0; nt < 4; nt++) {
                const int rb = warp_n * 32 + nt * 8 + grp;
                bh[nt] = ld_frag(Bhi, rb, ks2, qd);
                bl[nt] = ld_frag(Blo, rb, ks2, qd);
            }
#pragma unroll
            for (int mt = 0; mt < MT; mt++) {
                const int rowA = warp_m * (BM / 2) + mt * 16 + grp;
                uint4 hE = ld_frag(Ahi, rowA,     ks2, qd);
                uint4 hO = ld_frag(Ahi, rowA + 8, ks2, qd);
                uint4 lE = ld_frag(Alo, rowA,     ks2, qd);
                uint4 lO = ld_frag(Alo, rowA + 8, ks2, qd);
#pragma unroll
                for (int nt = 0; nt < 4; nt++) {
                    mma_tf32(acc[mt][nt][0], acc[mt][nt][1], acc[mt][nt][2], acc[mt][nt][3],
                             hE.x, hO.x, hE.y, hO.y, bh[nt].x, bh[nt].y);
                    mma_tf32(acc[mt][nt][0], acc[mt][nt][1], acc[mt][nt][2], acc[mt][nt][3],
                             hE.x, hO.x, hE.y, hO.y, bl[nt].x, bl[nt].y);
                    mma_tf32(acc[mt][nt][0], acc[mt][nt][1], acc[mt][nt][2], acc[mt][nt][3],
                             lE.x, lO.x, lE.y, lO.y, bh[nt].x, bh[nt].y);
                    mma_tf32(acc[mt][nt][0], acc[mt][nt][1], acc[mt][nt][2], acc[mt][nt][3],
                             hE.z, hO.z, hE.w, hO.w, bh[nt].z, bh[nt].w);
                    mma_tf32(acc[mt][nt][0], acc[mt][nt][1], acc[mt][nt][2], acc[mt][nt][3],
                             hE.z, hO.z, hE.w, hO.w, bl[nt].z, bl[nt].w);
                    mma_tf32(acc[mt][nt][0], acc[mt][nt][1], acc[mt][nt][2], acc[mt][nt][3],
                             lE.z, lO.z, lE.w, lO.w, bh[nt].z, bh[nt].w);
                }
            }
        }
        __syncthreads();
    }

    // epilogue
#pragma unroll
    for (int mt = 0; mt < MT; mt++) {
        const int r0 = bm + warp_m * (BM / 2) + mt * 16 + grp;
#pragma unroll
        for (int nt = 0; nt < 4; nt++) {
            const int c0 = bn + warp_n * 32 + nt * 8 + 2 * qd;
            const float bz0 = bias[c0], bz1 = bias[c0 + 1];
            float v00 = fmaxf(acc[mt][nt][0] + bz0, 0.f) * scale;
            float v01 = fmaxf(acc[mt][nt][1] + bz1, 0.f) * scale;
            float v10 = fmaxf(acc[mt][nt][2] + bz0, 0.f) * scale;
            float v11 = fmaxf(acc[mt][nt][3] + bz1, 0.f) * scale;
            if (Chi) {
                uint32_t h00 = f2tf32(v00), h01 = f2tf32(v01);
                uint32_t h10 = f2tf32(v10), h11 = f2tf32(v11);
                *reinterpret_cast<uint2*>(Chi + (size_t)r0 * Nout + c0)       = make_uint2(h00, h01);
                *reinterpret_cast<uint2*>(Chi + (size_t)(r0 + 8) * Nout + c0) = make_uint2(h10, h11);
                *reinterpret_cast<uint2*>(Clo + (size_t)r0 * Nout + c0) =
                    make_uint2(f2tf32(v00 - __uint_as_float(h00)), f2tf32(v01 - __uint_as_float(h01)));
                *reinterpret_cast<uint2*>(Clo + (size_t)(r0 + 8) * Nout + c0) =
                    make_uint2(f2tf32(v10 - __uint_as_float(h10)), f2tf32(v11 - __uint_as_float(h11)));
            }
            if (C2) {
                *reinterpret_cast<float2*>(C2 + (size_t)r0 * Nout + c0)       = make_float2(v00, v01);
                *reinterpret_cast<float2*>(C2 + (size_t)(r0 + 8) * Nout + c0) = make_float2(v10, v11);
            }
            if (Ctf) {
                *reinterpret_cast<uint2*>(Ctf + (size_t)r0 * Nout + c0) =
                    make_uint2(f2tf32(v00), f2tf32(v01));
                *reinterpret_cast<uint2*>(Ctf + (size_t)(r0 + 8) * Nout + c0) =
                    make_uint2(f2tf32(v10), f2tf32(v11));
            }
        }
    }
}

// ===========================================================================
// Tiled transpose: dst[c][r] = src[r][c]
// ===========================================================================
__global__ void transpose_k(const float* __restrict__ src, float* __restrict__ dst,
                            int R, int Cc)
{
    __shared__ float t[32][33];
    const int cb = blockIdx.x * 32, rb = blockIdx.y * 32;
    const int x = threadIdx.x, y = threadIdx.y;
#pragma unroll
    for (int i = 0; i < 32; i += 8) {
        const int r = rb + y + i, c = cb + x;
        if (r < R && c < Cc) t[y + i][x] = src[(size_t)r * Cc + c];
    }
    __syncthreads();
#pragma unroll
    for (int i = 0; i < 32; i += 8) {
        const int c = cb + y + i, r = rb + x;
        if (c < Cc && r < R) dst[(size_t)c * R + r] = t[x][y + i];
    }
}

// ===========================================================================
// Launch. _COEF = [5,0,0,0,0] exactly => all_h = 5*relu(relu(x@W1+b1)@W2+b2);
// src/dst/deg dead. Output = [recons (N,N), all_h (N,H)].
// ===========================================================================
extern "C" void kernel_launch(void* const* d_in, const int* in_sizes, int n_in,
                              void* d_out, int out_size)
{
    const float* in_feat = (const float*)d_in[0];
    const float* W1      = (const float*)d_in[3];
    const float* b1      = (const float*)d_in[4];
    const float* W2      = (const float*)d_in[5];
    const float* b2      = (const float*)d_in[6];
    float* out = (float*)d_out;

    const int H2   = in_sizes[4];                  // 256
    const int INd  = in_sizes[3] / H2;             // 256
    const int N    = in_sizes[0] / INd;            // 8192
    const int H    = in_sizes[6];                  // 128

    float *w1t, *w2t;
    uint32_t *h1hi, *h1lo, *ahtf;
    cudaGetSymbolAddress((void**)&w1t, g_W1T);
    cudaGetSymbolAddress((void**)&w2t, g_W2T);
    cudaGetSymbolAddress((void**)&h1hi, g_h1hi);
    cudaGetSymbolAddress((void**)&h1lo, g_h1lo);
    cudaGetSymbolAddress((void**)&ahtf, g_allh_tf);

    const int SM128 = (2 * 128 + 2 * 128) * 32 * 4;   // 65536
    const int SM64  = (2 * 64 + 2 * 128) * 32 * 4;    // 49152
    cudaFuncSetAttribute((const void*)gemm3t<128, false>,
                         cudaFuncAttributeMaxDynamicSharedMemorySize, SM128);
    cudaFuncSetAttribute((const void*)gemm3t<64, true>,
                         cudaFuncAttributeMaxDynamicSharedMemorySize, SM64);
    cudaFuncSetAttribute((const void*)recons_mma,
                         cudaFuncAttributeMaxDynamicSharedMemorySize, R_SMEM_BYTES);

    // 0) transpose weights (tiny)
    {
        dim3 blk(32, 8);
        transpose_k<<<dim3(H2 / 32, H2 / 32), blk>>>(W1, w1t, H2, H2);
        transpose_k<<<dim3(H / 32, H2 / 32), blk>>>(W2, w2t, H2, H);
    }
    // 1) h1 = relu(in_feat @ W1 + b1) -> pre-split hi/lo planes
    gemm3t<128, false><<<dim3(N / 128, H2 / 128), 256, SM128>>>(
        in_feat, nullptr, nullptr, w1t, b1, h1hi, h1lo, nullptr, nullptr, INd, H2, 1.0f);
    // 2) all_h = 5*relu(h1 @ W2 + b2) -> out tail (f32) + tf32 bits
    gemm3t<64, true><<<dim3(N / 64, H / 128), 256, SM64>>>(
        nullptr, h1hi, h1lo, w2t, b2, nullptr, nullptr, out + (size_t)N * N, ahtf, H2, H, 5.0f);
    // 3) recons = all_h @ all_h^T (packed-fragment tf32 mma, symmetric pairs)
    {
        const int NB = N / 128;                    // 64
        const int nblocks = NB * (NB + 1) / 2;     // 2080
        recons_mma<<<nblocks, 256, R_SMEM_BYTES>>>(ahtf, out, NB, N);
    }
}